// round 7
// baseline (speedup 1.0000x reference)
#include <cuda_runtime.h>

// QuantizedLinear(5 -> 10, bits=2) over 4M tokens, fp32.
// Bandwidth kernel: weights dequantized into REGISTERS once per thread,
// amortized over 8 tiles of 256 tokens; x/out staged through smem so all
// global traffic is coalesced float4.

#define THREADS 256
#define TPB 256                 // tokens per tile (1 per thread)
#define TILES 8                 // tiles per block
#define IN_F 5
#define OUT_F 10

__global__ __launch_bounds__(THREADS, 3)
void qlinear2bit_kernel(const float* __restrict__ x,
                        const float* __restrict__ w,
                        const float* __restrict__ bias,
                        float* __restrict__ out,
                        int n_tokens)
{
    __shared__ float sx[TPB * IN_F];     // 1280 floats = 5 KB
    __shared__ float so[TPB * OUT_F];    // 2560 floats = 10 KB

    const int t = threadIdx.x;

    // ---- dequantize weights + bias into registers (once per thread) ----
    float wd[OUT_F][IN_F];
    float b[OUT_F];
    #pragma unroll
    for (int o = 0; o < OUT_F; o++) {
        float m = 0.0f;
        #pragma unroll
        for (int c = 0; c < IN_F; c++) {
            wd[o][c] = __ldg(&w[o * IN_F + c]);
            m = fmaxf(m, fabsf(wd[o][c]));
        }
        float scale = fmaxf(m, 1e-8f);   // qmax = 2^(bits-1)-1 = 1
        float inv = 1.0f / scale;
        #pragma unroll
        for (int c = 0; c < IN_F; c++) {
            float q = rintf(wd[o][c] * inv);       // round-half-to-even == jnp.round
            q = fminf(fmaxf(q, -2.0f), 1.0f);      // clip [qmin, qmax]
            wd[o][c] = q * scale;
        }
        b[o] = __ldg(&bias[o]);
    }

    #pragma unroll 1
    for (int tile = 0; tile < TILES; tile++) {
        const long long tok0 =
            ((long long)blockIdx.x * TILES + tile) * TPB;
        if (tok0 >= (long long)n_tokens) break;

        // ---- coalesced load of x tile ----
        const long long xbase = tok0 * IN_F;
        const long long xtotal = (long long)n_tokens * IN_F;
        const int nf = (int)((xtotal - xbase < (long long)(TPB * IN_F))
                                 ? (xtotal - xbase) : (long long)(TPB * IN_F));
        if (nf == TPB * IN_F) {
            const float4* xg = (const float4*)(x + xbase);  // 5120B-aligned
            #pragma unroll
            for (int i = t; i < TPB * IN_F / 4; i += THREADS)
                ((float4*)sx)[i] = xg[i];
        } else {
            for (int i = t; i < nf; i += THREADS)
                sx[i] = x[xbase + i];
        }
        __syncthreads();

        // ---- compute: one token per thread, weights from registers ----
        if (tok0 + t < (long long)n_tokens) {
            float xi[IN_F];
            #pragma unroll
            for (int c = 0; c < IN_F; c++) xi[c] = sx[t * IN_F + c];
            #pragma unroll
            for (int o = 0; o < OUT_F; o++) {
                float acc = b[o];
                #pragma unroll
                for (int c = 0; c < IN_F; c++)
                    acc = fmaf(xi[c], wd[o][c], acc);
                so[t * OUT_F + o] = acc;
            }
        }
        __syncthreads();

        // ---- coalesced store of out tile ----
        const long long obase = tok0 * OUT_F;
        const long long ototal = (long long)n_tokens * OUT_F;
        const int nof = (int)((ototal - obase < (long long)(TPB * OUT_F))
                                  ? (ototal - obase) : (long long)(TPB * OUT_F));
        if (nof == TPB * OUT_F) {
            float4* og = (float4*)(out + obase);            // 10240B-aligned
            #pragma unroll
            for (int i = t; i < TPB * OUT_F / 4; i += THREADS)
                og[i] = ((const float4*)so)[i];
        } else {
            for (int i = t; i < nof; i += THREADS)
                out[obase + i] = so[i];
        }
        __syncthreads();   // so (and sx) must be fully read before next tile
    }
}

extern "C" void kernel_launch(void* const* d_in, const int* in_sizes, int n_in,
                              void* d_out, int out_size)
{
    const float* x    = (const float*)d_in[0];   // [N, 5]
    const float* w    = (const float*)d_in[1];   // [10, 5]
    const float* bias = (const float*)d_in[2];   // [10]
    float* out = (float*)d_out;                  // [N, 10]

    const int n_tokens = in_sizes[0] / IN_F;
    const int tokens_per_block = TPB * TILES;
    const int grid = (n_tokens + tokens_per_block - 1) / tokens_per_block;
    qlinear2bit_kernel<<<grid, THREADS>>>(x, w, bias, out, n_tokens);
}

// round 8
// speedup vs baseline: 1.0426x; 1.0426x over previous
#include <cuda_runtime.h>

// QuantizedLinear(5 -> 10, bits=2) over 4M tokens, fp32.
//
// Design: outputs split across thread PAIRS (even lane: outputs 0-4, odd
// lane: 5-9) so dequantized weights live in ~30 registers/thread without
// killing occupancy. Single-sync software pipeline with double-buffered
// x/out tiles: per iteration we prefetch next x tile (regs), stream out the
// previous out tile, and compute the current tile — DRAM latency hidden
// in-block. All global traffic is coalesced float4.

#define THREADS 256
#define TPT 128                 // tokens per tile (one thread PAIR per token)
#define TILES 8                 // tiles per block -> 1024 tokens/block
#define IN_F 5
#define OUT_F 10
#define XF (TPT * IN_F)         // 640 floats / x tile
#define OF (TPT * OUT_F)        // 1280 floats / out tile

__global__ __launch_bounds__(THREADS, 4)
void qlinear2bit_kernel(const float* __restrict__ x,
                        const float* __restrict__ w,
                        const float* __restrict__ bias,
                        float* __restrict__ out,
                        int n_tokens)
{
    __shared__ float sx[2][XF];     // 2 x 2.5 KB
    __shared__ float so[2][OF];     // 2 x 5 KB

    const int t = threadIdx.x;
    const int p = t >> 1;           // token within tile (0..127)
    const int h = t & 1;            // output half: rows h*5 .. h*5+4

    // ---- dequantize this thread's 5 weight rows into registers ----
    float wd[5][IN_F], b[5];
    #pragma unroll
    for (int j = 0; j < 5; j++) {
        const int o = h * 5 + j;
        float m = 0.0f;
        #pragma unroll
        for (int c = 0; c < IN_F; c++) {
            wd[j][c] = __ldg(&w[o * IN_F + c]);
            m = fmaxf(m, fabsf(wd[j][c]));
        }
        float scale = fmaxf(m, 1e-8f);          // qmax = 2^(bits-1)-1 = 1
        float inv = 1.0f / scale;
        #pragma unroll
        for (int c = 0; c < IN_F; c++) {
            float q = rintf(wd[j][c] * inv);    // round-half-even == jnp.round
            wd[j][c] = fminf(fmaxf(q, -2.0f), 1.0f) * scale;
        }
        b[j] = __ldg(&bias[o]);
    }

    const long long blk0 = (long long)blockIdx.x * (TPT * TILES);

    // ---- prologue: stage x tile 0 ----
    {
        const long long tok0 = blk0;
        if (tok0 < n_tokens) {
            if (tok0 + TPT <= (long long)n_tokens) {
                const float4* xg = (const float4*)(x + tok0 * IN_F);
                if (t < XF / 4) ((float4*)sx[0])[t] = xg[t];
            } else {
                const int nf = (int)((long long)n_tokens * IN_F - tok0 * IN_F);
                for (int i = t; i < nf; i += THREADS)
                    sx[0][i] = x[tok0 * IN_F + i];
            }
        }
    }
    __syncthreads();

    // ---- pipelined main loop (one extra iteration drains last out tile) ----
    for (int tile = 0; tile <= TILES; tile++) {
        const int cur = tile & 1;
        const long long tok0 = blk0 + (long long)tile * TPT;
        const bool cur_valid = (tile < TILES) && (tok0 < (long long)n_tokens);

        // 1) prefetch next x tile into registers (issue LDG early)
        const long long ntok0 = tok0 + TPT;
        const bool nxt_valid = (tile + 1 < TILES) && (ntok0 < (long long)n_tokens);
        const bool nxt_full  = nxt_valid && (ntok0 + TPT <= (long long)n_tokens);
        float4 pf = make_float4(0.f, 0.f, 0.f, 0.f);
        if (nxt_full && t < XF / 4)
            pf = ((const float4*)(x + ntok0 * IN_F))[t];

        // 2) stream out previous tile's results (so[cur^1] is complete)
        if (tile >= 1) {
            const long long ptok0 = tok0 - TPT;
            if (ptok0 < (long long)n_tokens) {
                if (ptok0 + TPT <= (long long)n_tokens) {
                    float4* og = (float4*)(out + ptok0 * OUT_F);
                    const float4* ss = (const float4*)so[cur ^ 1];
                    og[t] = ss[t];
                    if (t < OF / 4 - THREADS) og[THREADS + t] = ss[THREADS + t];
                } else {
                    const int nof = (int)((long long)n_tokens * OUT_F - ptok0 * OUT_F);
                    for (int i = t; i < nof; i += THREADS)
                        out[ptok0 * OUT_F + i] = so[cur ^ 1][i];
                }
            }
        }

        // 3) compute current tile: thread pair shares token p
        if (cur_valid && (tok0 + p < (long long)n_tokens)) {
            float xi[IN_F];
            #pragma unroll
            for (int c = 0; c < IN_F; c++)
                xi[c] = sx[cur][p * IN_F + c];       // pair-broadcast, no conflicts
            #pragma unroll
            for (int j = 0; j < 5; j++) {
                float acc = b[j];
                #pragma unroll
                for (int c = 0; c < IN_F; c++)
                    acc = fmaf(xi[c], wd[j][c], acc);
                so[cur][p * OUT_F + h * 5 + j] = acc; // even/odd banks disjoint
            }
        }

        // 4) commit prefetched x into the other buffer (STS waits on LDG here,
        //    after compute has already issued)
        if (nxt_full) {
            if (t < XF / 4) ((float4*)sx[cur ^ 1])[t] = pf;
        } else if (nxt_valid) {
            const int nf = (int)((long long)n_tokens * IN_F - ntok0 * IN_F);
            for (int i = t; i < nf; i += THREADS)
                sx[cur ^ 1][i] = x[ntok0 * IN_F + i];
        }

        __syncthreads();
    }
}

extern "C" void kernel_launch(void* const* d_in, const int* in_sizes, int n_in,
                              void* d_out, int out_size)
{
    const float* x    = (const float*)d_in[0];   // [N, 5]
    const float* w    = (const float*)d_in[1];   // [10, 5]
    const float* bias = (const float*)d_in[2];   // [10]
    float* out = (float*)d_out;                  // [N, 10]

    const int n_tokens = in_sizes[0] / IN_F;
    const int tokens_per_block = TPT * TILES;
    const int grid = (n_tokens + tokens_per_block - 1) / tokens_per_block;
    qlinear2bit_kernel<<<grid, THREADS>>>(x, w, bias, out, n_tokens);
}